// round 1
// baseline (speedup 1.0000x reference)
#include <cuda_runtime.h>

#define NN     10000
#define NE     320000
#define H      128
#define HID    256
#define KM     336   // 2*H + 64 + 16
#define KX     384   // H + HID
#define NSTEP  64
#define NLAYER 4

#define BM 128
#define BN 128
#define BK 16

// ---------------- static device scratch (no allocs allowed) ----------------
__device__ float g_soh[(size_t)NE * NSTEP];     // 81.9 MB
__device__ float g_maggr[(size_t)NN * HID];     // 10.2 MB
__device__ float g_xbuf[2][(size_t)NN * H];     // ping-pong x
__device__ float g_posbuf[2][(size_t)NN * 3];   // ping-pong pos
__device__ float g_posacc[(size_t)NN * 3];
__device__ float g_cnt[NN];

__device__ __forceinline__ float leaky(float v) { return v > 0.f ? v : 0.01f * v; }

// ---------------- small kernels ----------------
__global__ void cnt_hist(const int* __restrict__ ei, float* __restrict__ cnt) {
    int e = blockIdx.x * blockDim.x + threadIdx.x;
    if (e < NE) atomicAdd(&cnt[ei[e]], 1.f);
}

// one warp per edge: r = ||x_i - x_j||, soh = exp(-gamma (r - c_k)^2)
__global__ void soh_kernel(const float* __restrict__ x, const int* __restrict__ ei,
                           float* __restrict__ soh) {
    int gt = blockIdx.x * blockDim.x + threadIdx.x;
    int e = gt >> 5, lane = gt & 31;
    if (e >= NE) return;
    int i = ei[e], j = ei[NE + e];
    float4 a = ((const float4*)(x + (size_t)i * H))[lane];
    float4 b = ((const float4*)(x + (size_t)j * H))[lane];
    float dx = a.x - b.x, dy = a.y - b.y, dz = a.z - b.z, dw = a.w - b.w;
    float s = dx * dx + dy * dy + dz * dz + dw * dw;
#pragma unroll
    for (int o = 16; o; o >>= 1) s += __shfl_xor_sync(0xffffffffu, s, o);
    float r = sqrtf(s);
    const float step = 10.f / 63.f;
    float c0 = (2 * lane) * step, c1 = (2 * lane + 1) * step;
    float d0 = r - c0, d1 = r - c1;
    soh[(size_t)e * NSTEP + 2 * lane]     = __expf(-10.f * d0 * d0);
    soh[(size_t)e * NSTEP + 2 * lane + 1] = __expf(-10.f * d1 * d1);
}

// ---------------- edge MLP GEMM: m_ij = feat @ Wm + bm, scatter-add into m_aggr
// feat[e] = [x_i (128), x_j (128), soh (64), edge_attr (16)]   K = 336
__global__ __launch_bounds__(256) void edge_mlp(
    const float* __restrict__ x, const float* __restrict__ soh,
    const float* __restrict__ ea, const float* __restrict__ Wm,
    const float* __restrict__ bm, const int* __restrict__ ei,
    float* __restrict__ maggr)
{
    __shared__ float As[BK][BM];
    __shared__ float Bs[BK][BN];
    __shared__ int si[BM], sj[BM];
    int t = threadIdx.x;
    int e0 = blockIdx.x * BM;
    int n0 = blockIdx.y * BN;
    if (t < BM) { si[t] = ei[e0 + t]; sj[t] = ei[NE + e0 + t]; }
    __syncthreads();

    float acc[8][8];
#pragma unroll
    for (int i = 0; i < 8; i++)
#pragma unroll
        for (int j = 0; j < 8; j++) acc[i][j] = 0.f;

    int row0 = (t >> 4) << 3, col0 = (t & 15) << 3;
    int arow = t >> 1, akk = (t & 1) << 3;       // A loader: 2 threads/row, 8 k each
    int bkk = t >> 4, bcol = (t & 15) << 3;      // B loader: 16 threads/krow, 8 n each

    for (int k0 = 0; k0 < KM; k0 += BK) {
        const float* src;
        if (k0 < H)                src = x   + (size_t)si[arow] * H     + k0 + akk;
        else if (k0 < 2 * H)       src = x   + (size_t)sj[arow] * H     + (k0 - H) + akk;
        else if (k0 < 2 * H + NSTEP) src = soh + (size_t)(e0 + arow) * NSTEP + (k0 - 2 * H) + akk;
        else                       src = ea  + (size_t)(e0 + arow) * 16 + akk;  // 16-wide chunk
        float4 p0 = *(const float4*)src;
        float4 p1 = *(const float4*)(src + 4);
        As[akk + 0][arow] = p0.x; As[akk + 1][arow] = p0.y;
        As[akk + 2][arow] = p0.z; As[akk + 3][arow] = p0.w;
        As[akk + 4][arow] = p1.x; As[akk + 5][arow] = p1.y;
        As[akk + 6][arow] = p1.z; As[akk + 7][arow] = p1.w;

        const float* wsrc = Wm + (size_t)(k0 + bkk) * HID + n0 + bcol;
        float4 w0 = *(const float4*)wsrc;
        float4 w1 = *(const float4*)(wsrc + 4);
        Bs[bkk][bcol + 0] = w0.x; Bs[bkk][bcol + 1] = w0.y;
        Bs[bkk][bcol + 2] = w0.z; Bs[bkk][bcol + 3] = w0.w;
        Bs[bkk][bcol + 4] = w1.x; Bs[bkk][bcol + 5] = w1.y;
        Bs[bkk][bcol + 6] = w1.z; Bs[bkk][bcol + 7] = w1.w;
        __syncthreads();

#pragma unroll
        for (int kk = 0; kk < BK; kk++) {
            float4 a0 = *(const float4*)&As[kk][row0];
            float4 a1 = *(const float4*)&As[kk][row0 + 4];
            float4 b0 = *(const float4*)&Bs[kk][col0];
            float4 b1 = *(const float4*)&Bs[kk][col0 + 4];
            float a[8] = {a0.x, a0.y, a0.z, a0.w, a1.x, a1.y, a1.z, a1.w};
            float b[8] = {b0.x, b0.y, b0.z, b0.w, b1.x, b1.y, b1.z, b1.w};
#pragma unroll
            for (int i = 0; i < 8; i++)
#pragma unroll
                for (int j = 0; j < 8; j++) acc[i][j] += a[i] * b[j];
        }
        __syncthreads();
    }

    float bias[8];
#pragma unroll
    for (int j = 0; j < 8; j++) bias[j] = bm[n0 + col0 + j];
#pragma unroll
    for (int i = 0; i < 8; i++) {
        int dest = si[row0 + i];
        float* dst = maggr + (size_t)dest * HID + n0 + col0;
#pragma unroll
        for (int j = 0; j < 8; j++) atomicAdd(dst + j, acc[i][j] + bias[j]);
    }
}

// ---------------- node MLP: x' = leaky([x, m_aggr] @ Wx + bx)   K = 384, N = 128
__global__ __launch_bounds__(256) void node_mlp(
    const float* __restrict__ x, const float* __restrict__ maggr,
    const float* __restrict__ Wx, const float* __restrict__ bx,
    float* __restrict__ xout)
{
    __shared__ float As[BK][BM];
    __shared__ float Bs[BK][BM];
    int t = threadIdx.x;
    int m0 = blockIdx.x * BM;
    float acc[8][8];
#pragma unroll
    for (int i = 0; i < 8; i++)
#pragma unroll
        for (int j = 0; j < 8; j++) acc[i][j] = 0.f;

    int row0 = (t >> 4) << 3, col0 = (t & 15) << 3;
    int arow = t >> 1, akk = (t & 1) << 3;
    int bkk = t >> 4, bcol = (t & 15) << 3;
    int m = m0 + arow;

    for (int k0 = 0; k0 < KX; k0 += BK) {
        float v[8];
        if (m < NN) {
            const float* src = (k0 < H) ? x + (size_t)m * H + k0 + akk
                                        : maggr + (size_t)m * HID + (k0 - H) + akk;
            float4 p0 = *(const float4*)src;
            float4 p1 = *(const float4*)(src + 4);
            v[0] = p0.x; v[1] = p0.y; v[2] = p0.z; v[3] = p0.w;
            v[4] = p1.x; v[5] = p1.y; v[6] = p1.z; v[7] = p1.w;
        } else {
#pragma unroll
            for (int u = 0; u < 8; u++) v[u] = 0.f;
        }
#pragma unroll
        for (int u = 0; u < 8; u++) As[akk + u][arow] = v[u];

        const float* wsrc = Wx + (size_t)(k0 + bkk) * H + bcol;
        float4 w0 = *(const float4*)wsrc;
        float4 w1 = *(const float4*)(wsrc + 4);
        Bs[bkk][bcol + 0] = w0.x; Bs[bkk][bcol + 1] = w0.y;
        Bs[bkk][bcol + 2] = w0.z; Bs[bkk][bcol + 3] = w0.w;
        Bs[bkk][bcol + 4] = w1.x; Bs[bkk][bcol + 5] = w1.y;
        Bs[bkk][bcol + 6] = w1.z; Bs[bkk][bcol + 7] = w1.w;
        __syncthreads();

#pragma unroll
        for (int kk = 0; kk < BK; kk++) {
            float4 a0 = *(const float4*)&As[kk][row0];
            float4 a1 = *(const float4*)&As[kk][row0 + 4];
            float4 b0 = *(const float4*)&Bs[kk][col0];
            float4 b1 = *(const float4*)&Bs[kk][col0 + 4];
            float a[8] = {a0.x, a0.y, a0.z, a0.w, a1.x, a1.y, a1.z, a1.w};
            float b[8] = {b0.x, b0.y, b0.z, b0.w, b1.x, b1.y, b1.z, b1.w};
#pragma unroll
            for (int i = 0; i < 8; i++)
#pragma unroll
                for (int j = 0; j < 8; j++) acc[i][j] += a[i] * b[j];
        }
        __syncthreads();
    }

#pragma unroll
    for (int i = 0; i < 8; i++) {
        int mm = m0 + row0 + i;
        if (mm < NN) {
#pragma unroll
            for (int j = 0; j < 8; j++)
                xout[(size_t)mm * H + col0 + j] = leaky(acc[i][j] + bx[col0 + j]);
        }
    }
}

// ---------------- pos update ----------------
__global__ void pos_scatter(const int* __restrict__ ei, const float* __restrict__ pos,
                            float* __restrict__ acc) {
    int e = blockIdx.x * blockDim.x + threadIdx.x;
    if (e >= NE) return;
    int i = ei[e], j = ei[NE + e];
#pragma unroll
    for (int d = 0; d < 3; d++)
        atomicAdd(&acc[i * 3 + d], pos[i * 3 + d] - pos[j * 3 + d]);
}

__global__ void pos_update(const float* __restrict__ pos, const float* __restrict__ acc,
                           const float* __restrict__ cnt, float* __restrict__ out) {
    int idx = blockIdx.x * blockDim.x + threadIdx.x;
    if (idx >= NN * 3) return;
    int n = idx / 3;
    float c = fmaxf(cnt[n], 1.f);
    out[idx] = pos[idx] + acc[idx] / c;
}

// ---------------- final: out = [leaky(x_ori + x4), pos4] ----------------
__global__ void final_kernel(const float* __restrict__ xori, const float* __restrict__ x,
                             const float* __restrict__ pos, float* __restrict__ out) {
    int idx = blockIdx.x * blockDim.x + threadIdx.x;
    if (idx < NN * H) out[idx] = leaky(xori[idx] + x[idx]);
    else if (idx < NN * H + NN * 3) out[idx] = pos[idx - NN * H];
}

// ---------------- launch ----------------
extern "C" void kernel_launch(void* const* d_in, const int* in_sizes, int n_in,
                              void* d_out, int out_size) {
    const float* x   = (const float*)d_in[0];
    const float* pos = (const float*)d_in[1];
    const int*   ei  = (const int*)d_in[2];
    const float* ea  = (const float*)d_in[3];
    const float* Wm  = (const float*)d_in[4];
    const float* bm  = (const float*)d_in[5];
    // d_in[6] = Wp, d_in[7] = bp : dead code (alpha unused), skipped
    const float* Wx  = (const float*)d_in[8];
    const float* bx  = (const float*)d_in[9];
    float* out = (float*)d_out;

    float *soh, *maggr, *xb, *pb, *pacc, *cnt;
    cudaGetSymbolAddress((void**)&soh,   g_soh);
    cudaGetSymbolAddress((void**)&maggr, g_maggr);
    cudaGetSymbolAddress((void**)&xb,    g_xbuf);
    cudaGetSymbolAddress((void**)&pb,    g_posbuf);
    cudaGetSymbolAddress((void**)&pacc,  g_posacc);
    cudaGetSymbolAddress((void**)&cnt,   g_cnt);

    cudaMemsetAsync(cnt, 0, NN * sizeof(float));
    cnt_hist<<<(NE + 255) / 256, 256>>>(ei, cnt);

    const float* curx = x;
    const float* curp = pos;
    for (int l = 0; l < NLAYER; l++) {
        float* nx = xb + (size_t)(l & 1) * NN * H;
        float* np = pb + (size_t)(l & 1) * NN * 3;

        soh_kernel<<<(NE * 32 + 255) / 256, 256>>>(curx, ei, soh);
        cudaMemsetAsync(maggr, 0, (size_t)NN * HID * sizeof(float));
        dim3 g(NE / BM, HID / BN);
        edge_mlp<<<g, 256>>>(curx, soh, ea, Wm + (size_t)l * KM * HID,
                             bm + (size_t)l * HID, ei, maggr);
        node_mlp<<<(NN + BM - 1) / BM, 256>>>(curx, maggr, Wx + (size_t)l * KX * H,
                                              bx + (size_t)l * H, nx);

        cudaMemsetAsync(pacc, 0, (size_t)NN * 3 * sizeof(float));
        pos_scatter<<<(NE + 255) / 256, 256>>>(ei, curp, pacc);
        pos_update<<<(NN * 3 + 255) / 256, 256>>>(curp, pacc, cnt, np);

        curx = nx;
        curp = np;
    }

    int total = NN * H + NN * 3;
    final_kernel<<<(total + 255) / 256, 256>>>(x, curx, curp, out);
}

// round 2
// speedup vs baseline: 7.5885x; 7.5885x over previous
#include <cuda_runtime.h>

#define NN     10000
#define NE     320000
#define H      128
#define HID    256
#define KM     336   // 2*H + 64 + 16
#define KX     384   // H + HID
#define NSTEP  64
#define NLAYER 4

// ---------------- static device scratch ----------------
__device__ float g_F[(size_t)NN * KM];          // per-node feature rows [cnt*x | Σx_j | Σsoh | Σea]
__device__ float g_maggr[(size_t)NN * HID];
__device__ float g_xbuf[2][(size_t)NN * H];
__device__ float g_posbuf[2][(size_t)NN * 3];
__device__ int   g_cnt[NN];
__device__ int   g_rowptr[NN + 1];
__device__ int   g_cursor[NN];
__device__ int   g_colj[NE];
__device__ float g_cntf[NN];

__device__ __forceinline__ float leaky(float v) { return v > 0.f ? v : 0.01f * v; }

// ---------------- CSR construction (once per launch; edge_index is constant) ----------------
__global__ void cnt_hist(const int* __restrict__ ei, int* __restrict__ cnt) {
    int e = blockIdx.x * blockDim.x + threadIdx.x;
    if (e < NE) atomicAdd(&cnt[ei[e]], 1);
}

__global__ void scan_kernel(const int* __restrict__ cnt, int* __restrict__ rowptr,
                            int* __restrict__ cursor, float* __restrict__ cntf) {
    __shared__ int part[256];
    int t = threadIdx.x;
    const int chunk = (NN + 255) / 256;
    int start = t * chunk;
    int s = 0;
    for (int u = 0; u < chunk; u++) { int idx = start + u; if (idx < NN) s += cnt[idx]; }
    part[t] = s;
    __syncthreads();
    for (int off = 1; off < 256; off <<= 1) {
        int v = (t >= off) ? part[t - off] : 0;
        __syncthreads();
        part[t] += v;
        __syncthreads();
    }
    int run = (t == 0) ? 0 : part[t - 1];
    for (int u = 0; u < chunk; u++) {
        int idx = start + u;
        if (idx < NN) {
            rowptr[idx] = run; cursor[idx] = run;
            cntf[idx] = (float)cnt[idx];
            run += cnt[idx];
        }
    }
    if (t == 255) rowptr[NN] = part[255];
}

__global__ void build_csr(const int* __restrict__ ei, int* __restrict__ cursor,
                          int* __restrict__ colj) {
    int e = blockIdx.x * blockDim.x + threadIdx.x;
    if (e < NE) {
        int p = atomicAdd(&cursor[ei[e]], 1);
        colj[p] = ei[NE + e];
    }
}

// zero + accumulate Σ ea into F columns [320,336) — layer-invariant
__global__ void zero_ea(float* __restrict__ F) {
    int idx = blockIdx.x * blockDim.x + threadIdx.x;
    if (idx < NN * 16) F[(size_t)(idx >> 4) * KM + 320 + (idx & 15)] = 0.f;
}
__global__ void ea_scatter(const int* __restrict__ ei, const float* __restrict__ ea,
                           float* __restrict__ F) {
    int idx = blockIdx.x * blockDim.x + threadIdx.x;
    if (idx < NE * 16) {
        int e = idx >> 4, k = idx & 15;
        atomicAdd(&F[(size_t)ei[e] * KM + 320 + k], ea[idx]);
    }
}

// ---------------- per-layer CSR kernel: one warp per node ----------------
// builds F[n] = [cnt*x_n (128) | Σ x_j (128) | Σ soh (64) | (ea kept)]  and new pos
__global__ __launch_bounds__(256) void csr_layer(
    const float* __restrict__ x, const float* __restrict__ pos,
    const int* __restrict__ rowptr, const int* __restrict__ colj,
    const float* __restrict__ cntf, float* __restrict__ F, float* __restrict__ npos)
{
    int w = (blockIdx.x * blockDim.x + threadIdx.x) >> 5;
    int lane = threadIdx.x & 31;
    if (w >= NN) return;
    int beg = rowptr[w], end = rowptr[w + 1];
    float4 xi = ((const float4*)(x + (size_t)w * H))[lane];
    float4 xs = make_float4(0.f, 0.f, 0.f, 0.f);
    float s0 = 0.f, s1 = 0.f, ps = 0.f;
    const float step = 10.f / 63.f;
    float c0 = (2 * lane) * step, c1 = (2 * lane + 1) * step;

    for (int k = beg; k < end; k++) {
        int j = colj[k];
        float4 xj = ((const float4*)(x + (size_t)j * H))[lane];
        float dx = xi.x - xj.x, dy = xi.y - xj.y, dz = xi.z - xj.z, dw = xi.w - xj.w;
        float ss = dx * dx + dy * dy + dz * dz + dw * dw;
#pragma unroll
        for (int o = 16; o; o >>= 1) ss += __shfl_xor_sync(0xffffffffu, ss, o);
        float r = sqrtf(ss);
        float d0 = r - c0, d1 = r - c1;
        s0 += __expf(-10.f * d0 * d0);
        s1 += __expf(-10.f * d1 * d1);
        xs.x += xj.x; xs.y += xj.y; xs.z += xj.z; xs.w += xj.w;
        if (lane < 3) ps += pos[j * 3 + lane];
    }

    float cf = cntf[w];
    float* Fr = F + (size_t)w * KM;
    ((float4*)Fr)[lane]          = make_float4(cf * xi.x, cf * xi.y, cf * xi.z, cf * xi.w);
    ((float4*)(Fr + H))[lane]    = xs;
    ((float2*)(Fr + 2 * H))[lane] = make_float2(s0, s1);
    if (lane < 3) {
        float p = pos[w * 3 + lane];
        npos[w * 3 + lane] = p + (cf * p - ps) / fmaxf(cf, 1.f);
    }
}

// ---------------- m_aggr GEMM: [NN,336] @ [336,256] + cnt*bm ----------------
#define BM1 128
#define BN1 128
#define BK1 16
__global__ __launch_bounds__(256) void maggr_gemm(
    const float* __restrict__ F, const float* __restrict__ Wm,
    const float* __restrict__ bm, const float* __restrict__ cntf,
    float* __restrict__ maggr)
{
    __shared__ float As[BK1][BM1];
    __shared__ float Bs[BK1][BN1];
    int t = threadIdx.x;
    int m0 = blockIdx.x * BM1;
    int n0 = blockIdx.y * BN1;

    float acc[8][8];
#pragma unroll
    for (int i = 0; i < 8; i++)
#pragma unroll
        for (int j = 0; j < 8; j++) acc[i][j] = 0.f;

    int row0 = (t >> 4) << 3, col0 = (t & 15) << 3;
    int arow = t >> 1, akk = (t & 1) << 3;
    int bkk = t >> 4, bcol = (t & 15) << 3;
    int m = m0 + arow;

    for (int k0 = 0; k0 < KM; k0 += BK1) {
        float v[8];
        if (m < NN) {
            const float* src = F + (size_t)m * KM + k0 + akk;
            float4 p0 = *(const float4*)src;
            float4 p1 = *(const float4*)(src + 4);
            v[0] = p0.x; v[1] = p0.y; v[2] = p0.z; v[3] = p0.w;
            v[4] = p1.x; v[5] = p1.y; v[6] = p1.z; v[7] = p1.w;
        } else {
#pragma unroll
            for (int u = 0; u < 8; u++) v[u] = 0.f;
        }
#pragma unroll
        for (int u = 0; u < 8; u++) As[akk + u][arow] = v[u];

        const float* wsrc = Wm + (size_t)(k0 + bkk) * HID + n0 + bcol;
        float4 w0 = *(const float4*)wsrc;
        float4 w1 = *(const float4*)(wsrc + 4);
        Bs[bkk][bcol + 0] = w0.x; Bs[bkk][bcol + 1] = w0.y;
        Bs[bkk][bcol + 2] = w0.z; Bs[bkk][bcol + 3] = w0.w;
        Bs[bkk][bcol + 4] = w1.x; Bs[bkk][bcol + 5] = w1.y;
        Bs[bkk][bcol + 6] = w1.z; Bs[bkk][bcol + 7] = w1.w;
        __syncthreads();

#pragma unroll
        for (int kk = 0; kk < BK1; kk++) {
            float4 a0 = *(const float4*)&As[kk][row0];
            float4 a1 = *(const float4*)&As[kk][row0 + 4];
            float4 b0 = *(const float4*)&Bs[kk][col0];
            float4 b1 = *(const float4*)&Bs[kk][col0 + 4];
            float a[8] = {a0.x, a0.y, a0.z, a0.w, a1.x, a1.y, a1.z, a1.w};
            float b[8] = {b0.x, b0.y, b0.z, b0.w, b1.x, b1.y, b1.z, b1.w};
#pragma unroll
            for (int i = 0; i < 8; i++)
#pragma unroll
                for (int j = 0; j < 8; j++) acc[i][j] += a[i] * b[j];
        }
        __syncthreads();
    }

    float bias[8];
#pragma unroll
    for (int j = 0; j < 8; j++) bias[j] = bm[n0 + col0 + j];
#pragma unroll
    for (int i = 0; i < 8; i++) {
        int mm = m0 + row0 + i;
        if (mm < NN) {
            float cf = cntf[mm];
#pragma unroll
            for (int j = 0; j < 8; j++)
                maggr[(size_t)mm * HID + n0 + col0 + j] = acc[i][j] + cf * bias[j];
        }
    }
}

// ---------------- node MLP: leaky([x, m_aggr] @ Wx + bx)  [NN,384]@[384,128] ----------------
#define BM2 64
#define BN2 128
#define BK2 16
__global__ __launch_bounds__(256) void node_mlp(
    const float* __restrict__ x, const float* __restrict__ maggr,
    const float* __restrict__ Wx, const float* __restrict__ bx,
    float* __restrict__ xout)
{
    __shared__ float As[BK2][BM2];
    __shared__ float Bs[BK2][BN2];
    int t = threadIdx.x;
    int m0 = blockIdx.x * BM2;

    float acc[4][8];
#pragma unroll
    for (int i = 0; i < 4; i++)
#pragma unroll
        for (int j = 0; j < 8; j++) acc[i][j] = 0.f;

    int row0 = (t >> 4) << 2, col0 = (t & 15) << 3;
    int arow = t >> 2, akk = (t & 3) << 2;
    int bkk = t >> 4, bcol = (t & 15) << 3;
    int m = m0 + arow;

    for (int k0 = 0; k0 < KX; k0 += BK2) {
        float4 p0 = make_float4(0.f, 0.f, 0.f, 0.f);
        if (m < NN) {
            int k = k0 + akk;
            const float* src = (k < H) ? x + (size_t)m * H + k
                                       : maggr + (size_t)m * HID + (k - H);
            p0 = *(const float4*)src;
        }
        As[akk + 0][arow] = p0.x; As[akk + 1][arow] = p0.y;
        As[akk + 2][arow] = p0.z; As[akk + 3][arow] = p0.w;

        const float* wsrc = Wx + (size_t)(k0 + bkk) * H + bcol;
        float4 w0 = *(const float4*)wsrc;
        float4 w1 = *(const float4*)(wsrc + 4);
        Bs[bkk][bcol + 0] = w0.x; Bs[bkk][bcol + 1] = w0.y;
        Bs[bkk][bcol + 2] = w0.z; Bs[bkk][bcol + 3] = w0.w;
        Bs[bkk][bcol + 4] = w1.x; Bs[bkk][bcol + 5] = w1.y;
        Bs[bkk][bcol + 6] = w1.z; Bs[bkk][bcol + 7] = w1.w;
        __syncthreads();

#pragma unroll
        for (int kk = 0; kk < BK2; kk++) {
            float4 a0 = *(const float4*)&As[kk][row0];
            float4 b0 = *(const float4*)&Bs[kk][col0];
            float4 b1 = *(const float4*)&Bs[kk][col0 + 4];
            float a[4] = {a0.x, a0.y, a0.z, a0.w};
            float b[8] = {b0.x, b0.y, b0.z, b0.w, b1.x, b1.y, b1.z, b1.w};
#pragma unroll
            for (int i = 0; i < 4; i++)
#pragma unroll
                for (int j = 0; j < 8; j++) acc[i][j] += a[i] * b[j];
        }
        __syncthreads();
    }

#pragma unroll
    for (int i = 0; i < 4; i++) {
        int mm = m0 + row0 + i;
        if (mm < NN) {
#pragma unroll
            for (int j = 0; j < 8; j++)
                xout[(size_t)mm * H + col0 + j] = leaky(acc[i][j] + bx[col0 + j]);
        }
    }
}

// ---------------- final: out = [leaky(x_ori + x4), pos4] ----------------
__global__ void final_kernel(const float* __restrict__ xori, const float* __restrict__ x,
                             const float* __restrict__ pos, float* __restrict__ out) {
    int idx = blockIdx.x * blockDim.x + threadIdx.x;
    if (idx < NN * H) out[idx] = leaky(xori[idx] + x[idx]);
    else if (idx < NN * H + NN * 3) out[idx] = pos[idx - NN * H];
}

// ---------------- launch ----------------
extern "C" void kernel_launch(void* const* d_in, const int* in_sizes, int n_in,
                              void* d_out, int out_size) {
    const float* x   = (const float*)d_in[0];
    const float* pos = (const float*)d_in[1];
    const int*   ei  = (const int*)d_in[2];
    const float* ea  = (const float*)d_in[3];
    const float* Wm  = (const float*)d_in[4];
    const float* bm  = (const float*)d_in[5];
    // d_in[6] = Wp, d_in[7] = bp : dead code (alpha unused)
    const float* Wx  = (const float*)d_in[8];
    const float* bx  = (const float*)d_in[9];
    float* out = (float*)d_out;

    float *F, *maggr, *xb, *pb, *cntf;
    int *cnt, *rowptr, *cursor, *colj;
    cudaGetSymbolAddress((void**)&F,      g_F);
    cudaGetSymbolAddress((void**)&maggr,  g_maggr);
    cudaGetSymbolAddress((void**)&xb,     g_xbuf);
    cudaGetSymbolAddress((void**)&pb,     g_posbuf);
    cudaGetSymbolAddress((void**)&cnt,    g_cnt);
    cudaGetSymbolAddress((void**)&rowptr, g_rowptr);
    cudaGetSymbolAddress((void**)&cursor, g_cursor);
    cudaGetSymbolAddress((void**)&colj,   g_colj);
    cudaGetSymbolAddress((void**)&cntf,   g_cntf);

    // CSR + layer-invariant precompute
    cudaMemsetAsync(cnt, 0, NN * sizeof(int));
    cnt_hist<<<(NE + 255) / 256, 256>>>(ei, cnt);
    scan_kernel<<<1, 256>>>(cnt, rowptr, cursor, cntf);
    build_csr<<<(NE + 255) / 256, 256>>>(ei, cursor, colj);
    zero_ea<<<(NN * 16 + 255) / 256, 256>>>(F);
    ea_scatter<<<(NE * 16 + 255) / 256, 256>>>(ei, ea, F);

    const float* curx = x;
    const float* curp = pos;
    for (int l = 0; l < NLAYER; l++) {
        float* nx = xb + (size_t)(l & 1) * NN * H;
        float* np = pb + (size_t)(l & 1) * NN * 3;

        csr_layer<<<(NN * 32 + 255) / 256, 256>>>(curx, curp, rowptr, colj, cntf, F, np);
        dim3 g1((NN + BM1 - 1) / BM1, HID / BN1);
        maggr_gemm<<<g1, 256>>>(F, Wm + (size_t)l * KM * HID, bm + (size_t)l * HID,
                                cntf, maggr);
        node_mlp<<<(NN + BM2 - 1) / BM2, 256>>>(curx, maggr, Wx + (size_t)l * KX * H,
                                                bx + (size_t)l * H, nx);
        curx = nx;
        curp = np;
    }

    int total = NN * H + NN * 3;
    final_kernel<<<(total + 255) / 256, 256>>>(x, curx, curp, out);
}

// round 3
// speedup vs baseline: 8.9535x; 1.1799x over previous
#include <cuda_runtime.h>

#define NN     10000
#define NE     320000
#define H      128
#define HID    256
#define KM     336   // 2*H + 64 + 16  (F row width)
#define KX     384   // H + HID
#define KA     464   // H + KM         (fused GEMM K)
#define NSTEP  64
#define NLAYER 4

// ---------------- static device scratch ----------------
__device__ float g_F[(size_t)NN * KM];            // [cnt*x | Σx_j | Σsoh | Σea]
__device__ float g_xbuf[2][(size_t)NN * H];
__device__ float g_posbuf[2][(size_t)NN * 3];
__device__ int   g_cnt[NN];
__device__ int   g_rowptr[NN + 1];
__device__ int   g_cursor[NN];
__device__ int   g_colj[NE];
__device__ float g_cntf[NN];
__device__ float g_Wall[(size_t)NLAYER * KA * H]; // [Wx1 (128 rows) ; Wm@Wx2 (336 rows)]
__device__ float g_bmx[NLAYER * H];               // bm @ Wx2

__device__ __forceinline__ float leaky(float v) { return v > 0.f ? v : 0.01f * v; }

// ---------------- preamble kernels ----------------
// zero cnt and the ea columns of F
__global__ void zero_init(float* __restrict__ F, int* __restrict__ cnt) {
    int idx = blockIdx.x * blockDim.x + threadIdx.x;
    if (idx < NN * 16) F[(size_t)(idx >> 4) * KM + 320 + (idx & 15)] = 0.f;
    if (idx < NN) cnt[idx] = 0;
}

__global__ void cnt_hist(const int* __restrict__ ei, int* __restrict__ cnt) {
    int e = blockIdx.x * blockDim.x + threadIdx.x;
    if (e < NE) atomicAdd(&cnt[ei[e]], 1);
}

__global__ void ea_scatter(const int* __restrict__ ei, const float* __restrict__ ea,
                           float* __restrict__ F) {
    int idx = blockIdx.x * blockDim.x + threadIdx.x;
    if (idx < NE * 16) {
        int e = idx >> 4, k = idx & 15;
        atomicAdd(&F[(size_t)ei[e] * KM + 320 + k], ea[idx]);
    }
}

__global__ void scan_kernel(const int* __restrict__ cnt, int* __restrict__ rowptr,
                            int* __restrict__ cursor, float* __restrict__ cntf) {
    __shared__ int part[256];
    int t = threadIdx.x;
    const int chunk = (NN + 255) / 256;
    int start = t * chunk;
    int s = 0;
    for (int u = 0; u < chunk; u++) { int idx = start + u; if (idx < NN) s += cnt[idx]; }
    part[t] = s;
    __syncthreads();
    for (int off = 1; off < 256; off <<= 1) {
        int v = (t >= off) ? part[t - off] : 0;
        __syncthreads();
        part[t] += v;
        __syncthreads();
    }
    int run = (t == 0) ? 0 : part[t - 1];
    for (int u = 0; u < chunk; u++) {
        int idx = start + u;
        if (idx < NN) {
            rowptr[idx] = run; cursor[idx] = run;
            cntf[idx] = (float)cnt[idx];
            run += cnt[idx];
        }
    }
    if (t == 255) rowptr[NN] = part[255];
}

__global__ void build_csr(const int* __restrict__ ei, int* __restrict__ cursor,
                          int* __restrict__ colj) {
    int e = blockIdx.x * blockDim.x + threadIdx.x;
    if (e < NE) {
        int p = atomicAdd(&cursor[ei[e]], 1);
        colj[p] = ei[NE + e];
    }
}

// fold Wm through Wx2:  Wall[l] = [ Wx1 ; Wm@Wx2 ],  bmx[l] = bm@Wx2
// grid (NLAYER, KA+1), block 128 (one thread per output column n)
__global__ void prep_weights(const float* __restrict__ Wm, const float* __restrict__ bm,
                             const float* __restrict__ Wx,
                             float* __restrict__ Wall, float* __restrict__ bmx) {
    int l = blockIdx.x, y = blockIdx.y, n = threadIdx.x;
    const float* WxL = Wx + (size_t)l * KX * H;
    float* WallL = Wall + (size_t)l * KA * H;
    if (y < H) {                                   // copy Wx1 row
        WallL[(size_t)y * H + n] = WxL[(size_t)y * H + n];
    } else if (y < KA) {                           // Wc row = Wm[row] @ Wx2
        int r = y - H;
        const float* wm = Wm + (size_t)l * KM * HID + (size_t)r * HID;
        float s = 0.f;
#pragma unroll 8
        for (int h = 0; h < HID; h++) s += wm[h] * WxL[(size_t)(H + h) * H + n];
        WallL[(size_t)y * H + n] = s;
    } else {                                       // bmx = bm @ Wx2
        const float* bmL = bm + (size_t)l * HID;
        float s = 0.f;
#pragma unroll 8
        for (int h = 0; h < HID; h++) s += bmL[h] * WxL[(size_t)(H + h) * H + n];
        bmx[l * H + n] = s;
    }
}

// ---------------- per-layer CSR kernel: one warp per node ----------------
// builds F[n] = [cnt*x_n (128) | Σ x_j (128) | Σ soh (64) | (ea kept)]  and new pos
__global__ __launch_bounds__(256) void csr_layer(
    const float* __restrict__ x, const float* __restrict__ pos,
    const int* __restrict__ rowptr, const int* __restrict__ colj,
    const float* __restrict__ cntf, float* __restrict__ F, float* __restrict__ npos)
{
    int w = (blockIdx.x * blockDim.x + threadIdx.x) >> 5;
    int lane = threadIdx.x & 31;
    if (w >= NN) return;
    int beg = rowptr[w], end = rowptr[w + 1];
    float4 xi = ((const float4*)(x + (size_t)w * H))[lane];
    float4 xs = make_float4(0.f, 0.f, 0.f, 0.f);
    float s0 = 0.f, s1 = 0.f, ps = 0.f;
    const float step = 10.f / 63.f;
    float c0 = (2 * lane) * step, c1 = (2 * lane + 1) * step;

    for (int k = beg; k < end; k++) {
        int j = colj[k];
        float4 xj = ((const float4*)(x + (size_t)j * H))[lane];
        float dx = xi.x - xj.x, dy = xi.y - xj.y, dz = xi.z - xj.z, dw = xi.w - xj.w;
        float ss = dx * dx + dy * dy + dz * dz + dw * dw;
#pragma unroll
        for (int o = 16; o; o >>= 1) ss += __shfl_xor_sync(0xffffffffu, ss, o);
        float r = sqrtf(ss);
        float d0 = r - c0, d1 = r - c1;
        s0 += __expf(-10.f * d0 * d0);
        s1 += __expf(-10.f * d1 * d1);
        xs.x += xj.x; xs.y += xj.y; xs.z += xj.z; xs.w += xj.w;
        if (lane < 3) ps += pos[j * 3 + lane];
    }

    float cf = cntf[w];
    float* Fr = F + (size_t)w * KM;
    ((float4*)Fr)[lane]           = make_float4(cf * xi.x, cf * xi.y, cf * xi.z, cf * xi.w);
    ((float4*)(Fr + H))[lane]     = xs;
    ((float2*)(Fr + 2 * H))[lane] = make_float2(s0, s1);
    if (lane < 3) {
        float p = pos[w * 3 + lane];
        npos[w * 3 + lane] = p + (cf * p - ps) / fmaxf(cf, 1.f);
    }
}

// ---------------- fused layer GEMM: x' = leaky([x|F] @ Wall + bx + cnt*bmx) ----------------
// [NN, 464] @ [464, 128];  BM=32, BN=128, BK=16, 256 threads, 2x8 micro-tile
__global__ __launch_bounds__(256) void fused_layer_gemm(
    const float* __restrict__ x, const float* __restrict__ F,
    const float* __restrict__ Wall, const float* __restrict__ bx,
    const float* __restrict__ bmx, const float* __restrict__ cntf,
    float* __restrict__ xout)
{
    __shared__ float As[16][32];
    __shared__ float Bs[16][128];
    int t = threadIdx.x;
    int m0 = blockIdx.x * 32;

    float acc[2][8];
#pragma unroll
    for (int i = 0; i < 2; i++)
#pragma unroll
        for (int j = 0; j < 8; j++) acc[i][j] = 0.f;

    int row0 = (t >> 4) << 1, col0 = (t & 15) << 3;
    int arow = t >> 3, akk = (t & 7) << 1;
    int bkk = t >> 4, bcol = (t & 15) << 3;
    int m = m0 + arow;

    for (int k0 = 0; k0 < KA; k0 += 16) {
        int k = k0 + akk;
        float2 av = make_float2(0.f, 0.f);
        if (m < NN) {
            const float* src = (k < H) ? x + (size_t)m * H + k
                                       : F + (size_t)m * KM + (k - H);
            av = *(const float2*)src;
        }
        As[akk][arow] = av.x;
        As[akk + 1][arow] = av.y;

        const float* wsrc = Wall + (size_t)(k0 + bkk) * H + bcol;
        float4 w0 = *(const float4*)wsrc;
        float4 w1 = *(const float4*)(wsrc + 4);
        Bs[bkk][bcol + 0] = w0.x; Bs[bkk][bcol + 1] = w0.y;
        Bs[bkk][bcol + 2] = w0.z; Bs[bkk][bcol + 3] = w0.w;
        Bs[bkk][bcol + 4] = w1.x; Bs[bkk][bcol + 5] = w1.y;
        Bs[bkk][bcol + 6] = w1.z; Bs[bkk][bcol + 7] = w1.w;
        __syncthreads();

#pragma unroll
        for (int kk = 0; kk < 16; kk++) {
            float2 a2 = *(const float2*)&As[kk][row0];
            float4 b0 = *(const float4*)&Bs[kk][col0];
            float4 b1 = *(const float4*)&Bs[kk][col0 + 4];
            float a[2] = {a2.x, a2.y};
            float b[8] = {b0.x, b0.y, b0.z, b0.w, b1.x, b1.y, b1.z, b1.w};
#pragma unroll
            for (int i = 0; i < 2; i++)
#pragma unroll
                for (int j = 0; j < 8; j++) acc[i][j] += a[i] * b[j];
        }
        __syncthreads();
    }

    float biasx[8], biasm[8];
#pragma unroll
    for (int j = 0; j < 8; j++) { biasx[j] = bx[col0 + j]; biasm[j] = bmx[col0 + j]; }
#pragma unroll
    for (int i = 0; i < 2; i++) {
        int mm = m0 + row0 + i;
        if (mm < NN) {
            float cf = cntf[mm];
#pragma unroll
            for (int j = 0; j < 8; j++)
                xout[(size_t)mm * H + col0 + j] = leaky(acc[i][j] + biasx[j] + cf * biasm[j]);
        }
    }
}

// ---------------- final: out = [leaky(x_ori + x4), pos4] ----------------
__global__ void final_kernel(const float* __restrict__ xori, const float* __restrict__ x,
                             const float* __restrict__ pos, float* __restrict__ out) {
    int idx = blockIdx.x * blockDim.x + threadIdx.x;
    if (idx < NN * H) out[idx] = leaky(xori[idx] + x[idx]);
    else if (idx < NN * H + NN * 3) out[idx] = pos[idx - NN * H];
}

// ---------------- launch ----------------
extern "C" void kernel_launch(void* const* d_in, const int* in_sizes, int n_in,
                              void* d_out, int out_size) {
    const float* x   = (const float*)d_in[0];
    const float* pos = (const float*)d_in[1];
    const int*   ei  = (const int*)d_in[2];
    const float* ea  = (const float*)d_in[3];
    const float* Wm  = (const float*)d_in[4];
    const float* bm  = (const float*)d_in[5];
    // d_in[6] = Wp, d_in[7] = bp : dead code (alpha unused)
    const float* Wx  = (const float*)d_in[8];
    const float* bx  = (const float*)d_in[9];
    float* out = (float*)d_out;

    float *F, *xb, *pb, *cntf, *Wall, *bmx;
    int *cnt, *rowptr, *cursor, *colj;
    cudaGetSymbolAddress((void**)&F,      g_F);
    cudaGetSymbolAddress((void**)&xb,     g_xbuf);
    cudaGetSymbolAddress((void**)&pb,     g_posbuf);
    cudaGetSymbolAddress((void**)&cnt,    g_cnt);
    cudaGetSymbolAddress((void**)&rowptr, g_rowptr);
    cudaGetSymbolAddress((void**)&cursor, g_cursor);
    cudaGetSymbolAddress((void**)&colj,   g_colj);
    cudaGetSymbolAddress((void**)&cntf,   g_cntf);
    cudaGetSymbolAddress((void**)&Wall,   g_Wall);
    cudaGetSymbolAddress((void**)&bmx,    g_bmx);

    // preamble: CSR build + ea segment-sum + weight folding
    zero_init<<<(NN * 16 + 255) / 256, 256>>>(F, cnt);
    cnt_hist<<<(NE + 255) / 256, 256>>>(ei, cnt);
    ea_scatter<<<(NE * 16 + 255) / 256, 256>>>(ei, ea, F);
    scan_kernel<<<1, 256>>>(cnt, rowptr, cursor, cntf);
    build_csr<<<(NE + 255) / 256, 256>>>(ei, cursor, colj);

    const float* curx = x;
    const float* curp = pos;
    for (int l = 0; l < NLAYER; l++) {
        float* nx = xb + (size_t)(l & 1) * NN * H;
        float* np = pb + (size_t)(l & 1) * NN * 3;

        csr_layer<<<(NN * 32 + 255) / 256, 256>>>(curx, curp, rowptr, colj, cntf, F, np);
        if (l == 0) {
            dim3 gp(NLAYER, KA + 1);
            prep_weights<<<gp, 128>>>(Wm, bm, Wx, Wall, bmx);  // independent; overlaps csr
        }
        fused_layer_gemm<<<(NN + 31) / 32, 256>>>(curx, F, Wall + (size_t)l * KA * H,
                                                  bx + (size_t)l * H, bmx + l * H,
                                                  cntf, nx);
        curx = nx;
        curp = np;
    }

    int total = NN * H + NN * 3;
    final_kernel<<<(total + 255) / 256, 256>>>(x, curx, curp, out);
}

// round 4
// speedup vs baseline: 11.8519x; 1.3237x over previous
#include <cuda_runtime.h>

#define NN     10000
#define NE     320000
#define H      128
#define HID    256
#define KM     336   // 2*H + 64 + 16  (F row width)
#define KX     384   // H + HID
#define KA     464   // H + KM         (fused GEMM K)
#define NSTEP  64
#define NLAYER 4

// ---------------- static device scratch ----------------
__device__ float g_F[(size_t)NN * KM];            // [cnt*x | Σx_j | Σsoh | Σea]
__device__ float g_xbuf[2][(size_t)NN * H];
__device__ float g_posbuf[2][(size_t)NN * 3];
__device__ int   g_cnt[NN];
__device__ int   g_rowptr[NN + 1];
__device__ int   g_cursor[NN];
__device__ int   g_colj[NE];
__device__ float g_cntf[NN];
__device__ float g_Wall[(size_t)NLAYER * KA * H]; // [Wx1 (128 rows) ; Wm@Wx2 (336 rows)]
__device__ float g_bmx[NLAYER * H];               // bm @ Wx2

__device__ __forceinline__ float leaky(float v) { return v > 0.f ? v : 0.01f * v; }

// ---------------- preamble kernels ----------------
__global__ void zero_init(float* __restrict__ F, int* __restrict__ cnt) {
    int idx = blockIdx.x * blockDim.x + threadIdx.x;
    if (idx < NN * 16) F[(size_t)(idx >> 4) * KM + 320 + (idx & 15)] = 0.f;
    if (idx < NN) cnt[idx] = 0;
}

// fused: degree histogram + Sigma(ea) scatter, one pass over edges
__global__ void edge_pre(const int* __restrict__ ei, const float* __restrict__ ea,
                         int* __restrict__ cnt, float* __restrict__ F) {
    int idx = blockIdx.x * blockDim.x + threadIdx.x;
    if (idx < NE * 16) {
        int e = idx >> 4, k = idx & 15;
        int dst = ei[e];
        atomicAdd(&F[(size_t)dst * KM + 320 + k], ea[idx]);
        if (k == 0) atomicAdd(&cnt[dst], 1);
    }
}

// 1024-thread hierarchical scan over NN=10000 degrees
__global__ void scan_kernel(const int* __restrict__ cnt, int* __restrict__ rowptr,
                            int* __restrict__ cursor, float* __restrict__ cntf) {
    __shared__ int wsum[32];
    int t = threadIdx.x;
    int lane = t & 31, wid = t >> 5;
    const int CH = 10;                    // 1024*10 >= 10000
    int base = t * CH;
    int v[CH];
    int s = 0;
#pragma unroll
    for (int u = 0; u < CH; u++) {
        int idx = base + u;
        v[u] = (idx < NN) ? cnt[idx] : 0;
        s += v[u];
    }
    int sc = s;
#pragma unroll
    for (int o = 1; o < 32; o <<= 1) {
        int n = __shfl_up_sync(0xffffffffu, sc, o);
        if (lane >= o) sc += n;
    }
    if (lane == 31) wsum[wid] = sc;
    __syncthreads();
    if (wid == 0) {
        int w = wsum[lane];
#pragma unroll
        for (int o = 1; o < 32; o <<= 1) {
            int n = __shfl_up_sync(0xffffffffu, w, o);
            if (lane >= o) w += n;
        }
        wsum[lane] = w;
    }
    __syncthreads();
    int run = sc - s + (wid ? wsum[wid - 1] : 0);
#pragma unroll
    for (int u = 0; u < CH; u++) {
        int idx = base + u;
        if (idx < NN) {
            rowptr[idx] = run; cursor[idx] = run;
            cntf[idx] = (float)v[u];
            run += v[u];
        }
    }
    if (t == 1023) rowptr[NN] = wsum[31];
}

__global__ void build_csr(const int* __restrict__ ei, int* __restrict__ cursor,
                          int* __restrict__ colj) {
    int e = blockIdx.x * blockDim.x + threadIdx.x;
    if (e < NE) {
        int p = atomicAdd(&cursor[ei[e]], 1);
        colj[p] = ei[NE + e];
    }
}

// fold Wm through Wx2:  Wall[l] = [ Wx1 ; Wm@Wx2 ],  bmx[l] = bm@Wx2
__global__ void prep_weights(const float* __restrict__ Wm, const float* __restrict__ bm,
                             const float* __restrict__ Wx,
                             float* __restrict__ Wall, float* __restrict__ bmx) {
    int l = blockIdx.x, y = blockIdx.y, n = threadIdx.x;
    const float* WxL = Wx + (size_t)l * KX * H;
    float* WallL = Wall + (size_t)l * KA * H;
    if (y < H) {
        WallL[(size_t)y * H + n] = WxL[(size_t)y * H + n];
    } else if (y < KA) {
        int r = y - H;
        const float* wm = Wm + (size_t)l * KM * HID + (size_t)r * HID;
        float s = 0.f;
#pragma unroll 8
        for (int h = 0; h < HID; h++) s += wm[h] * WxL[(size_t)(H + h) * H + n];
        WallL[(size_t)y * H + n] = s;
    } else {
        const float* bmL = bm + (size_t)l * HID;
        float s = 0.f;
#pragma unroll 8
        for (int h = 0; h < HID; h++) s += bmL[h] * WxL[(size_t)(H + h) * H + n];
        bmx[l * H + n] = s;
    }
}

// ---------------- per-layer CSR kernel: one warp per node, 2-deep prefetch ----------------
__global__ __launch_bounds__(256) void csr_layer(
    const float* __restrict__ x, const float* __restrict__ pos,
    const int* __restrict__ rowptr, const int* __restrict__ colj,
    const float* __restrict__ cntf, float* __restrict__ F, float* __restrict__ npos)
{
    int w = (blockIdx.x * blockDim.x + threadIdx.x) >> 5;
    int lane = threadIdx.x & 31;
    if (w >= NN) return;
    int beg = rowptr[w], end = rowptr[w + 1];
    float4 xi = ((const float4*)(x + (size_t)w * H))[lane];
    float4 xs = make_float4(0.f, 0.f, 0.f, 0.f);
    float s0 = 0.f, s1 = 0.f, ps = 0.f;
    const float step = 10.f / 63.f;
    float c0 = (2 * lane) * step, c1 = (2 * lane + 1) * step;

    // prefetch edge k
    int   jn = 0;
    float4 xjn = make_float4(0.f, 0.f, 0.f, 0.f);
    float pjn = 0.f;
    if (beg < end) {
        jn = colj[beg];
        xjn = ((const float4*)(x + (size_t)jn * H))[lane];
        if (lane < 3) pjn = pos[jn * 3 + lane];
    }
    for (int k = beg; k < end; k++) {
        int j = jn;
        float4 xj = xjn;
        float pj = pjn;
        if (k + 1 < end) {                        // issue next gather before reduce
            jn = colj[k + 1];
            xjn = ((const float4*)(x + (size_t)jn * H))[lane];
            if (lane < 3) pjn = pos[jn * 3 + lane];
        }
        float dx = xi.x - xj.x, dy = xi.y - xj.y, dz = xi.z - xj.z, dw = xi.w - xj.w;
        float ss = dx * dx + dy * dy + dz * dz + dw * dw;
#pragma unroll
        for (int o = 16; o; o >>= 1) ss += __shfl_xor_sync(0xffffffffu, ss, o);
        float r = sqrtf(ss);
        float d0 = r - c0, d1 = r - c1;
        s0 += __expf(-10.f * d0 * d0);
        s1 += __expf(-10.f * d1 * d1);
        xs.x += xj.x; xs.y += xj.y; xs.z += xj.z; xs.w += xj.w;
        ps += pj;
    }

    float cf = cntf[w];
    float* Fr = F + (size_t)w * KM;
    ((float4*)Fr)[lane]           = make_float4(cf * xi.x, cf * xi.y, cf * xi.z, cf * xi.w);
    ((float4*)(Fr + H))[lane]     = xs;
    ((float2*)(Fr + 2 * H))[lane] = make_float2(s0, s1);
    if (lane < 3) {
        float p = pos[w * 3 + lane];
        npos[w * 3 + lane] = p + (cf * p - ps) / fmaxf(cf, 1.f);
    }
}

// ---------------- fused layer GEMM: x' = leaky([x|F] @ Wall + bx + cnt*bmx) ----------------
// optional residual epilogue (last layer): out = leaky(resid + x')
// [NN,464]@[464,128]; BM=32, BN=128, BK=16, 128 threads, 4x8 micro-tile
__global__ __launch_bounds__(128) void fused_layer_gemm(
    const float* __restrict__ x, const float* __restrict__ F,
    const float* __restrict__ Wall, const float* __restrict__ bx,
    const float* __restrict__ bmx, const float* __restrict__ cntf,
    const float* __restrict__ resid, float* __restrict__ xout)
{
    __shared__ float As[16][32];
    __shared__ float Bs[16][128];
    int t = threadIdx.x;
    int m0 = blockIdx.x * 32;

    float acc[4][8];
#pragma unroll
    for (int i = 0; i < 4; i++)
#pragma unroll
        for (int j = 0; j < 8; j++) acc[i][j] = 0.f;

    int row0 = (t >> 4) << 2;          // 0,4,...,28 (two values per warp)
    int col0 = (t & 15) << 3;          // 0..120
    int arow = t >> 2, akk = (t & 3) << 2;   // A: 32 rows x 4 k each
    int bkk = t >> 3, bcol = (t & 7) << 4;   // B: 16 krows x 16 cols each
    int m = m0 + arow;

    for (int k0 = 0; k0 < KA; k0 += 16) {
        int k = k0 + akk;
        float4 av = make_float4(0.f, 0.f, 0.f, 0.f);
        if (m < NN) {
            const float* src = (k < H) ? x + (size_t)m * H + k
                                       : F + (size_t)m * KM + (k - H);
            av = *(const float4*)src;
        }
        As[akk + 0][arow] = av.x; As[akk + 1][arow] = av.y;
        As[akk + 2][arow] = av.z; As[akk + 3][arow] = av.w;

        const float* wsrc = Wall + (size_t)(k0 + bkk) * H + bcol;
        float4 w0 = *(const float4*)wsrc;
        float4 w1 = *(const float4*)(wsrc + 4);
        float4 w2 = *(const float4*)(wsrc + 8);
        float4 w3 = *(const float4*)(wsrc + 12);
        *(float4*)&Bs[bkk][bcol + 0]  = w0;
        *(float4*)&Bs[bkk][bcol + 4]  = w1;
        *(float4*)&Bs[bkk][bcol + 8]  = w2;
        *(float4*)&Bs[bkk][bcol + 12] = w3;
        __syncthreads();

#pragma unroll
        for (int kk = 0; kk < 16; kk++) {
            float4 a0 = *(const float4*)&As[kk][row0];
            float4 b0 = *(const float4*)&Bs[kk][col0];
            float4 b1 = *(const float4*)&Bs[kk][col0 + 4];
            float a[4] = {a0.x, a0.y, a0.z, a0.w};
            float b[8] = {b0.x, b0.y, b0.z, b0.w, b1.x, b1.y, b1.z, b1.w};
#pragma unroll
            for (int i = 0; i < 4; i++)
#pragma unroll
                for (int j = 0; j < 8; j++) acc[i][j] += a[i] * b[j];
        }
        __syncthreads();
    }

    float biasx[8], biasm[8];
#pragma unroll
    for (int j = 0; j < 8; j++) { biasx[j] = bx[col0 + j]; biasm[j] = bmx[col0 + j]; }
#pragma unroll
    for (int i = 0; i < 4; i++) {
        int mm = m0 + row0 + i;
        if (mm < NN) {
            float cf = cntf[mm];
#pragma unroll
            for (int j = 0; j < 8; j++) {
                float v = leaky(acc[i][j] + biasx[j] + cf * biasm[j]);
                if (resid) v = leaky(resid[(size_t)mm * H + col0 + j] + v);
                xout[(size_t)mm * H + col0 + j] = v;
            }
        }
    }
}

// ---------------- launch ----------------
extern "C" void kernel_launch(void* const* d_in, const int* in_sizes, int n_in,
                              void* d_out, int out_size) {
    const float* x   = (const float*)d_in[0];
    const float* pos = (const float*)d_in[1];
    const int*   ei  = (const int*)d_in[2];
    const float* ea  = (const float*)d_in[3];
    const float* Wm  = (const float*)d_in[4];
    const float* bm  = (const float*)d_in[5];
    // d_in[6] = Wp, d_in[7] = bp : dead code (alpha unused)
    const float* Wx  = (const float*)d_in[8];
    const float* bx  = (const float*)d_in[9];
    float* out = (float*)d_out;

    float *F, *xb, *pb, *cntf, *Wall, *bmx;
    int *cnt, *rowptr, *cursor, *colj;
    cudaGetSymbolAddress((void**)&F,      g_F);
    cudaGetSymbolAddress((void**)&xb,     g_xbuf);
    cudaGetSymbolAddress((void**)&pb,     g_posbuf);
    cudaGetSymbolAddress((void**)&cnt,    g_cnt);
    cudaGetSymbolAddress((void**)&rowptr, g_rowptr);
    cudaGetSymbolAddress((void**)&cursor, g_cursor);
    cudaGetSymbolAddress((void**)&colj,   g_colj);
    cudaGetSymbolAddress((void**)&cntf,   g_cntf);
    cudaGetSymbolAddress((void**)&Wall,   g_Wall);
    cudaGetSymbolAddress((void**)&bmx,    g_bmx);

    // preamble
    {
        dim3 gp(NLAYER, KA + 1);
        prep_weights<<<gp, 128>>>(Wm, bm, Wx, Wall, bmx);
    }
    zero_init<<<(NN * 16 + 255) / 256, 256>>>(F, cnt);
    edge_pre<<<(NE * 16 + 255) / 256, 256>>>(ei, ea, cnt, F);
    scan_kernel<<<1, 1024>>>(cnt, rowptr, cursor, cntf);
    build_csr<<<(NE + 255) / 256, 256>>>(ei, cursor, colj);

    const float* curx = x;
    const float* curp = pos;
    for (int l = 0; l < NLAYER; l++) {
        bool last = (l == NLAYER - 1);
        float* nx = last ? out : xb + (size_t)(l & 1) * NN * H;
        float* np = last ? out + (size_t)NN * H : pb + (size_t)(l & 1) * NN * 3;

        csr_layer<<<(NN * 32 + 255) / 256, 256>>>(curx, curp, rowptr, colj, cntf, F, np);
        fused_layer_gemm<<<(NN + 31) / 32, 128>>>(curx, F, Wall + (size_t)l * KA * H,
                                                  bx + (size_t)l * H, bmx + l * H,
                                                  cntf, last ? x : nullptr, nx);
        curx = nx;
        curp = np;
    }
}

// round 5
// speedup vs baseline: 15.3285x; 1.2933x over previous
#include <cuda_runtime.h>
#include <cstdint>

#define NN     10000
#define NE     320000
#define H      128
#define HID    256
#define KM     336   // 2*H + 64 + 16  (F row width)
#define KX     384   // H + HID
#define KA     464   // H + KM         (fused GEMM K)
#define NSTEP  64
#define NLAYER 4

// ---------------- static device scratch ----------------
__device__ float g_F[(size_t)NN * KM];            // [cnt*x | Σx_j | Σsoh | Σea]
__device__ float g_xbuf[2][(size_t)NN * H];
__device__ float g_posbuf[2][(size_t)NN * 3];
__device__ int   g_cnt[NN];
__device__ int   g_rowptr[NN + 1];
__device__ int   g_cursor[NN];
__device__ int   g_colj[NE];
__device__ float g_cntf[NN];
__device__ float g_Wall[(size_t)NLAYER * KA * H]; // [Wx1 (128 rows) ; Wm@Wx2 (336 rows)]
__device__ float g_bmx[NLAYER * H];               // bm @ Wx2

__device__ __forceinline__ float leaky(float v) { return v > 0.f ? v : 0.01f * v; }
__device__ __forceinline__ float tf32_rna(float x) {
    float r; asm("cvt.rna.tf32.f32 %0, %1;" : "=f"(r) : "f"(x)); return r;
}
__device__ __forceinline__ void mma8(float* d, const uint32_t* a, const uint32_t* b) {
    asm volatile(
        "mma.sync.aligned.m16n8k8.row.col.f32.tf32.tf32.f32 "
        "{%0,%1,%2,%3}, {%4,%5,%6,%7}, {%8,%9}, {%0,%1,%2,%3};"
        : "+f"(d[0]), "+f"(d[1]), "+f"(d[2]), "+f"(d[3])
        : "r"(a[0]), "r"(a[1]), "r"(a[2]), "r"(a[3]), "r"(b[0]), "r"(b[1]));
}

// ---------------- preamble kernels ----------------
__global__ void zero_init(float* __restrict__ F, int* __restrict__ cnt) {
    int idx = blockIdx.x * blockDim.x + threadIdx.x;
    if (idx < NN * 16) F[(size_t)(idx >> 4) * KM + 320 + (idx & 15)] = 0.f;
    if (idx < NN) cnt[idx] = 0;
}

__global__ void edge_pre(const int* __restrict__ ei, const float* __restrict__ ea,
                         int* __restrict__ cnt, float* __restrict__ F) {
    int idx = blockIdx.x * blockDim.x + threadIdx.x;
    if (idx < NE * 16) {
        int e = idx >> 4, k = idx & 15;
        int dst = ei[e];
        atomicAdd(&F[(size_t)dst * KM + 320 + k], ea[idx]);
        if (k == 0) atomicAdd(&cnt[dst], 1);
    }
}

// coalesced-staged hierarchical scan
__global__ void scan_kernel(const int* __restrict__ cnt, int* __restrict__ rowptr,
                            int* __restrict__ cursor, float* __restrict__ cntf) {
    __shared__ int sc[NN];
    __shared__ int wsum[32];
    int t = threadIdx.x;
    for (int i = t; i < NN; i += 1024) sc[i] = cnt[i];
    __syncthreads();
    int lane = t & 31, wid = t >> 5;
    const int CH = 10;
    int base = t * CH;
    int v[CH];
    int s = 0;
#pragma unroll
    for (int u = 0; u < CH; u++) {
        int idx = base + u;
        v[u] = (idx < NN) ? sc[idx] : 0;
        s += v[u];
    }
    int scn = s;
#pragma unroll
    for (int o = 1; o < 32; o <<= 1) {
        int n = __shfl_up_sync(0xffffffffu, scn, o);
        if (lane >= o) scn += n;
    }
    if (lane == 31) wsum[wid] = scn;
    __syncthreads();
    if (wid == 0) {
        int w = wsum[lane];
#pragma unroll
        for (int o = 1; o < 32; o <<= 1) {
            int n = __shfl_up_sync(0xffffffffu, w, o);
            if (lane >= o) w += n;
        }
        wsum[lane] = w;
    }
    __syncthreads();
    int run = scn - s + (wid ? wsum[wid - 1] : 0);
#pragma unroll
    for (int u = 0; u < CH; u++) {
        int idx = base + u;
        if (idx < NN) {
            rowptr[idx] = run; cursor[idx] = run;
            cntf[idx] = (float)v[u];
            run += v[u];
        }
    }
    if (t == 1023) rowptr[NN] = wsum[31];
}

__global__ void build_csr(const int* __restrict__ ei, int* __restrict__ cursor,
                          int* __restrict__ colj) {
    int e = blockIdx.x * blockDim.x + threadIdx.x;
    if (e < NE) {
        int p = atomicAdd(&cursor[ei[e]], 1);
        colj[p] = ei[NE + e];
    }
}

// fold Wm through Wx2:  Wall[l] = [ Wx1 ; Wm@Wx2 ],  bmx[l] = bm@Wx2
__global__ void prep_weights(const float* __restrict__ Wm, const float* __restrict__ bm,
                             const float* __restrict__ Wx,
                             float* __restrict__ Wall, float* __restrict__ bmx) {
    int l = blockIdx.x, y = blockIdx.y, n = threadIdx.x;
    const float* WxL = Wx + (size_t)l * KX * H;
    float* WallL = Wall + (size_t)l * KA * H;
    if (y < H) {
        WallL[(size_t)y * H + n] = WxL[(size_t)y * H + n];
    } else if (y < KA) {
        int r = y - H;
        const float* wm = Wm + (size_t)l * KM * HID + (size_t)r * HID;
        float s = 0.f;
#pragma unroll 8
        for (int h = 0; h < HID; h++) s += wm[h] * WxL[(size_t)(H + h) * H + n];
        WallL[(size_t)y * H + n] = s;
    } else {
        const float* bmL = bm + (size_t)l * HID;
        float s = 0.f;
#pragma unroll 8
        for (int h = 0; h < HID; h++) s += bmL[h] * WxL[(size_t)(H + h) * H + n];
        bmx[l * H + n] = s;
    }
}

// ---------------- per-layer CSR kernel: one warp per node ----------------
__global__ __launch_bounds__(256) void csr_layer(
    const float* __restrict__ x, const float* __restrict__ pos,
    const int* __restrict__ rowptr, const int* __restrict__ colj,
    const float* __restrict__ cntf, float* __restrict__ F, float* __restrict__ npos)
{
    int w = (blockIdx.x * blockDim.x + threadIdx.x) >> 5;
    int lane = threadIdx.x & 31;
    if (w >= NN) return;
    int beg = rowptr[w], end = rowptr[w + 1];
    float4 xi = ((const float4*)(x + (size_t)w * H))[lane];
    float4 xs = make_float4(0.f, 0.f, 0.f, 0.f);
    float s0 = 0.f, s1 = 0.f, ps = 0.f;
    const float step = 10.f / 63.f;
    float c0 = (2 * lane) * step, c1 = (2 * lane + 1) * step;

    int jn = 0, jn2 = 0;
    float4 xjn = make_float4(0.f, 0.f, 0.f, 0.f);
    float pjn = 0.f;
    if (beg < end) {
        jn = colj[beg];
        xjn = ((const float4*)(x + (size_t)jn * H))[lane];
        if (lane < 3) pjn = pos[jn * 3 + lane];
    }
    if (beg + 1 < end) jn2 = colj[beg + 1];

    for (int k = beg; k < end; k++) {
        float4 xj = xjn;
        float pj = pjn;
        int jcur = jn2;
        jn = jn2;
        if (k + 2 < end) jn2 = colj[k + 2];
        if (k + 1 < end) {
            xjn = ((const float4*)(x + (size_t)jcur * H))[lane];
            if (lane < 3) pjn = pos[jcur * 3 + lane];
        }
        float dx = xi.x - xj.x, dy = xi.y - xj.y, dz = xi.z - xj.z, dw = xi.w - xj.w;
        float ss = dx * dx + dy * dy + dz * dz + dw * dw;
#pragma unroll
        for (int o = 16; o; o >>= 1) ss += __shfl_xor_sync(0xffffffffu, ss, o);
        float r = sqrtf(ss);
        float d0 = r - c0, d1 = r - c1;
        s0 += __expf(-10.f * d0 * d0);
        s1 += __expf(-10.f * d1 * d1);
        xs.x += xj.x; xs.y += xj.y; xs.z += xj.z; xs.w += xj.w;
        ps += pj;
    }

    float cf = cntf[w];
    float* Fr = F + (size_t)w * KM;
    ((float4*)Fr)[lane]           = make_float4(cf * xi.x, cf * xi.y, cf * xi.z, cf * xi.w);
    ((float4*)(Fr + H))[lane]     = xs;
    ((float2*)(Fr + 2 * H))[lane] = make_float2(s0, s1);
    if (lane < 3) {
        float p = pos[w * 3 + lane];
        npos[w * 3 + lane] = p + (cf * p - ps) / fmaxf(cf, 1.f);
    }
}

// ---------------- fused layer GEMM (3xTF32 tensor cores) ----------------
// x' = leaky([x|F] @ Wall + bx + cnt*bmx)   [NN,464]@[464,128]
// BM=64 BN=128 BK=16, 256 thr, 8 warps (2x4), warp tile 32x32
#define NKT 29   // KA/16
__global__ __launch_bounds__(256) void fused_layer_gemm(
    const float* __restrict__ x, const float* __restrict__ F,
    const float* __restrict__ Wall, const float* __restrict__ bx,
    const float* __restrict__ bmx, const float* __restrict__ cntf,
    const float* __restrict__ resid, float* __restrict__ xout)
{
    __shared__ float Ah[64][20], Al[64][20];
    __shared__ float Bh[16][132], Bl[16][132];

    int t = threadIdx.x;
    int m0 = blockIdx.x * 64;
    int wid = t >> 5, lane = t & 31;
    int g = lane >> 2, c = lane & 3;
    int mb = (wid >> 2) * 32, nb = (wid & 3) * 32;

    // loader coords
    int am = t & 63, akq = (t >> 6) << 2;           // A: row am, 4 k
    int bk = t >> 4, bn = (t & 15) << 3;            // B: row bk, 8 n
    int mm = m0 + am; if (mm >= NN) mm = NN - 1;
    const float* rowx = x + (size_t)mm * H;
    const float* rowF = F + (size_t)mm * KM - H;    // so rowF[k] = F[m][k-128]

    float acc[2][4][4];
#pragma unroll
    for (int i = 0; i < 2; i++)
#pragma unroll
        for (int j = 0; j < 4; j++)
#pragma unroll
            for (int q = 0; q < 4; q++) acc[i][j][q] = 0.f;

    // preload tile 0
    float4 aR; float4 bR0, bR1;
    {
        int k = akq;
        aR = *(const float4*)((k < H ? rowx : rowF) + k);
        const float* wsrc = Wall + (size_t)bk * H + bn;
        bR0 = *(const float4*)wsrc;
        bR1 = *(const float4*)(wsrc + 4);
    }

    for (int it = 0; it < NKT; it++) {
        // split + store to smem
        {
            float h0 = tf32_rna(aR.x), h1 = tf32_rna(aR.y),
                  h2 = tf32_rna(aR.z), h3 = tf32_rna(aR.w);
            Ah[am][akq+0] = h0; Ah[am][akq+1] = h1; Ah[am][akq+2] = h2; Ah[am][akq+3] = h3;
            Al[am][akq+0] = tf32_rna(aR.x - h0); Al[am][akq+1] = tf32_rna(aR.y - h1);
            Al[am][akq+2] = tf32_rna(aR.z - h2); Al[am][akq+3] = tf32_rna(aR.w - h3);

            float p0 = tf32_rna(bR0.x), p1 = tf32_rna(bR0.y),
                  p2 = tf32_rna(bR0.z), p3 = tf32_rna(bR0.w);
            float p4 = tf32_rna(bR1.x), p5 = tf32_rna(bR1.y),
                  p6 = tf32_rna(bR1.z), p7 = tf32_rna(bR1.w);
            Bh[bk][bn+0] = p0; Bh[bk][bn+1] = p1; Bh[bk][bn+2] = p2; Bh[bk][bn+3] = p3;
            Bh[bk][bn+4] = p4; Bh[bk][bn+5] = p5; Bh[bk][bn+6] = p6; Bh[bk][bn+7] = p7;
            Bl[bk][bn+0] = tf32_rna(bR0.x - p0); Bl[bk][bn+1] = tf32_rna(bR0.y - p1);
            Bl[bk][bn+2] = tf32_rna(bR0.z - p2); Bl[bk][bn+3] = tf32_rna(bR0.w - p3);
            Bl[bk][bn+4] = tf32_rna(bR1.x - p4); Bl[bk][bn+5] = tf32_rna(bR1.y - p5);
            Bl[bk][bn+6] = tf32_rna(bR1.z - p6); Bl[bk][bn+7] = tf32_rna(bR1.w - p7);
        }
        __syncthreads();

        // prefetch next tile
        if (it + 1 < NKT) {
            int k0n = (it + 1) * 16;
            int k = k0n + akq;
            aR = *(const float4*)((k < H ? rowx : rowF) + k);
            const float* wsrc = Wall + (size_t)(k0n + bk) * H + bn;
            bR0 = *(const float4*)wsrc;
            bR1 = *(const float4*)(wsrc + 4);
        }

        // compute: 2 k8 sub-steps
#pragma unroll
        for (int ks = 0; ks < 16; ks += 8) {
            uint32_t ah[2][4], al[2][4], bh[4][2], bl[4][2];
#pragma unroll
            for (int mt = 0; mt < 2; mt++) {
                int r0 = mb + mt * 16 + g, r1 = r0 + 8;
                ah[mt][0] = __float_as_uint(Ah[r0][ks + c]);
                ah[mt][1] = __float_as_uint(Ah[r1][ks + c]);
                ah[mt][2] = __float_as_uint(Ah[r0][ks + c + 4]);
                ah[mt][3] = __float_as_uint(Ah[r1][ks + c + 4]);
                al[mt][0] = __float_as_uint(Al[r0][ks + c]);
                al[mt][1] = __float_as_uint(Al[r1][ks + c]);
                al[mt][2] = __float_as_uint(Al[r0][ks + c + 4]);
                al[mt][3] = __float_as_uint(Al[r1][ks + c + 4]);
            }
#pragma unroll
            for (int nt = 0; nt < 4; nt++) {
                int nc = nb + nt * 8 + g;
                bh[nt][0] = __float_as_uint(Bh[ks + c][nc]);
                bh[nt][1] = __float_as_uint(Bh[ks + c + 4][nc]);
                bl[nt][0] = __float_as_uint(Bl[ks + c][nc]);
                bl[nt][1] = __float_as_uint(Bl[ks + c + 4][nc]);
            }
#pragma unroll
            for (int mt = 0; mt < 2; mt++)
#pragma unroll
                for (int nt = 0; nt < 4; nt++) {
                    mma8(acc[mt][nt], al[mt], bh[nt]);   // lo*hi
                    mma8(acc[mt][nt], ah[mt], bl[nt]);   // hi*lo
                    mma8(acc[mt][nt], ah[mt], bh[nt]);   // hi*hi
                }
        }
        __syncthreads();
    }

    // epilogue
#pragma unroll
    for (int mt = 0; mt < 2; mt++) {
        int r0 = m0 + mb + mt * 16 + g;
        int r1 = r0 + 8;
        float cf0 = (r0 < NN) ? cntf[r0] : 0.f;
        float cf1 = (r1 < NN) ? cntf[r1] : 0.f;
#pragma unroll
        for (int nt = 0; nt < 4; nt++) {
            int col = nb + nt * 8 + 2 * c;
            float bx0 = bx[col], bx1 = bx[col + 1];
            float bm0 = bmx[col], bm1 = bmx[col + 1];
            if (r0 < NN) {
                float v0 = leaky(acc[mt][nt][0] + bx0 + cf0 * bm0);
                float v1 = leaky(acc[mt][nt][1] + bx1 + cf0 * bm1);
                if (resid) {
                    v0 = leaky(resid[(size_t)r0 * H + col] + v0);
                    v1 = leaky(resid[(size_t)r0 * H + col + 1] + v1);
                }
                *(float2*)&xout[(size_t)r0 * H + col] = make_float2(v0, v1);
            }
            if (r1 < NN) {
                float v2 = leaky(acc[mt][nt][2] + bx0 + cf1 * bm0);
                float v3 = leaky(acc[mt][nt][3] + bx1 + cf1 * bm1);
                if (resid) {
                    v2 = leaky(resid[(size_t)r1 * H + col] + v2);
                    v3 = leaky(resid[(size_t)r1 * H + col + 1] + v3);
                }
                *(float2*)&xout[(size_t)r1 * H + col] = make_float2(v2, v3);
            }
        }
    }
}

// ---------------- launch ----------------
extern "C" void kernel_launch(void* const* d_in, const int* in_sizes, int n_in,
                              void* d_out, int out_size) {
    const float* x   = (const float*)d_in[0];
    const float* pos = (const float*)d_in[1];
    const int*   ei  = (const int*)d_in[2];
    const float* ea  = (const float*)d_in[3];
    const float* Wm  = (const float*)d_in[4];
    const float* bm  = (const float*)d_in[5];
    // d_in[6] = Wp, d_in[7] = bp : dead code (alpha unused)
    const float* Wx  = (const float*)d_in[8];
    const float* bx  = (const float*)d_in[9];
    float* out = (float*)d_out;

    float *F, *xb, *pb, *cntf, *Wall, *bmx;
    int *cnt, *rowptr, *cursor, *colj;
    cudaGetSymbolAddress((void**)&F,      g_F);
    cudaGetSymbolAddress((void**)&xb,     g_xbuf);
    cudaGetSymbolAddress((void**)&pb,     g_posbuf);
    cudaGetSymbolAddress((void**)&cnt,    g_cnt);
    cudaGetSymbolAddress((void**)&rowptr, g_rowptr);
    cudaGetSymbolAddress((void**)&cursor, g_cursor);
    cudaGetSymbolAddress((void**)&colj,   g_colj);
    cudaGetSymbolAddress((void**)&cntf,   g_cntf);
    cudaGetSymbolAddress((void**)&Wall,   g_Wall);
    cudaGetSymbolAddress((void**)&bmx,    g_bmx);

    {
        dim3 gp(NLAYER, KA + 1);
        prep_weights<<<gp, 128>>>(Wm, bm, Wx, Wall, bmx);
    }
    zero_init<<<(NN * 16 + 255) / 256, 256>>>(F, cnt);
    edge_pre<<<(NE * 16 + 255) / 256, 256>>>(ei, ea, cnt, F);
    scan_kernel<<<1, 1024>>>(cnt, rowptr, cursor, cntf);
    build_csr<<<(NE + 255) / 256, 256>>>(ei, cursor, colj);

    const float* curx = x;
    const float* curp = pos;
    for (int l = 0; l < NLAYER; l++) {
        bool last = (l == NLAYER - 1);
        float* nx = last ? out : xb + (size_t)(l & 1) * NN * H;
        float* np = last ? out + (size_t)NN * H : pb + (size_t)(l & 1) * NN * 3;

        csr_layer<<<(NN * 32 + 255) / 256, 256>>>(curx, curp, rowptr, colj, cntf, F, np);
        fused_layer_gemm<<<(NN + 63) / 64, 256>>>(curx, F, Wall + (size_t)l * KA * H,
                                                  bx + (size_t)l * H, bmx + l * H,
                                                  cntf, last ? x : nullptr, nx);
        curx = nx;
        curp = np;
    }
}